// round 11
// baseline (speedup 1.0000x reference)
#include <cuda_runtime.h>
#include <math.h>

#define XD 128
#define NDEPTH 222
#define MPAD 256
// max_extent = sqrt(3*(64^2)) * 1.5
static constexpr double MAX_EXTENT_D = 166.27687752661222232;
static constexpr double DT_D         = 2.0 * MAX_EXTENT_D / (NDEPTH - 1);
static constexpr double SCALE_D      = 2.0 * MAX_EXTENT_D / NDEPTH;

__device__ __forceinline__ void slab_axis(float r, float b, float& tlo, float& thi, bool& empty) {
    if (fabsf(r) > 1e-12f) {
        float inv = __frcp_rn(r);
        float ta = (-1.0f - b) * inv;
        float tb = (128.0f - b) * inv;
        tlo = fmaxf(tlo, fminf(ta, tb));
        thi = fminf(thi, fmaxf(ta, tb));
    } else if (b <= -1.0f || b >= 128.0f) {
        empty = true;
    }
}

// Interval (i0, cnt) of in-volume depth steps for a ray with base (bx,by).
__device__ __forceinline__ void rayInterval(float rx, float ry, float bx, float by,
                                            int& i0, int& cnt) {
    const float t0 = (float)(-MAX_EXTENT_D);
    const float dt = (float)DT_D;
    float tlo = -3.0e38f, thi = 3.0e38f;
    bool empty = false;
    slab_axis(rx, bx, tlo, thi, empty);
    slab_axis(ry, by, tlo, thi, empty);
    i0 = 0; cnt = 0;
    if (!empty && thi >= tlo) {
        i0 = max(0, (int)ceilf((tlo - t0) / dt) - 1);
        int i1 = min(NDEPTH - 1, (int)floorf((thi - t0) / dt) + 1);
        cnt = i1 - i0 + 1;
        if (cnt < 0) cnt = 0;
    }
}

__global__ void __launch_bounds__(256, 4)
projector_kernel(const float* __restrict__ vol,
                 const float* __restrict__ vec,
                 float* __restrict__ out) {
    const int tid = threadIdx.x;
    const int p   = blockIdx.x;          // pair index: rays jA = p, jB = p + 64
    const int n   = blockIdx.y;

    const float* V = vec + n * 12;
    const float rx = __ldg(V + 0), ry = __ldg(V + 1), rz = __ldg(V + 2);
    const float dx = __ldg(V + 3), dy = __ldg(V + 4), dz = __ldg(V + 5);
    const float ux = __ldg(V + 6), uy = __ldg(V + 7), uz = __ldg(V + 8);
    const float vx = __ldg(V + 9), vy = __ldg(V + 10), vz = __ldg(V + 11);

    const float t0 = (float)(-MAX_EXTENT_D);
    const float dt = (float)DT_D;

    __shared__ int4   As[MPAD];        // row byte-offsets: A entries [0,LA), B entries [LA,LA+LB)
    __shared__ float4 Ws[MPAD];        // bilinear weights
    __shared__ float  Red[2][8][132];  // per-ray padded reduce buffers

    // Fast path: z-axis-aligned geometry -> per-ray-uniform (x,y) sample,
    // z index is EXACTLY the pixel k with fz = 0 (single z-tap, weight 1).
    // In-square chord <= sqrt(2)*129/dt + 2 < 128 steps, so each ray's list fits 128.
    const bool fast = (rz == 0.0f) & (uz == 0.0f) & (dz == 0.0f) &
                      (vx == 0.0f) & (vy == 0.0f) & (vz == 1.0f);

    const int jA = p;
    const int jB = p + 64;
    const float jcA = (float)jA - 63.5f;
    const float jcB = (float)jB - 63.5f;

    if (fast) {
        const int w    = tid >> 5;   // warp id (0..7)
        const int lane = tid & 31;   // covers z = 4*lane .. 4*lane+3

        const float bxA = fmaf(jcA, ux, dx) + 63.5f;
        const float byA = fmaf(jcA, uy, dy) + 63.5f;
        const float bxB = fmaf(jcB, ux, dx) + 63.5f;
        const float byB = fmaf(jcB, uy, dy) + 63.5f;

        int i0A, cntA, i0B, cntB;
        rayInterval(rx, ry, bxA, byA, i0A, cntA);
        rayInterval(rx, ry, bxB, byB, i0B, cntB);
        const int LA = (cntA + 15) & ~15;    // <= 128
        const int LB = (cntB + 15) & ~15;    // <= 128

        // Metadata: thread (r = tid>>7, s = tid&127) fills slot s of ray r's list.
        {
            const int r = tid >> 7;
            const int s = tid & 127;
            const int Lr   = r ? LB : LA;
            const int cntr = r ? cntB : cntA;
            const int base = r ? LA : 0;
            if (s < Lr) {
                if (s < cntr) {
                    const int   i0r = r ? i0B : i0A;
                    const float bx  = r ? bxB : bxA;
                    const float by  = r ? byB : byA;
                    const float t  = fmaf((float)(i0r + s), dt, t0);
                    const float px = fmaf(t, rx, bx);
                    const float py = fmaf(t, ry, by);
                    const float x0f = floorf(px);
                    const float y0f = floorf(py);
                    const float fx = px - x0f;
                    const float fy = py - y0f;
                    const int x0 = (int)x0f;
                    const int y0 = (int)y0f;
                    const float wx0 = ((unsigned)x0       < (unsigned)XD) ? (1.0f - fx) : 0.0f;
                    const float wx1 = ((unsigned)(x0 + 1) < (unsigned)XD) ? fx          : 0.0f;
                    const float wy0 = ((unsigned)y0       < (unsigned)XD) ? (1.0f - fy) : 0.0f;
                    const float wy1 = ((unsigned)(y0 + 1) < (unsigned)XD) ? fy          : 0.0f;
                    const int xc0 = min(max(x0, 0), XD - 1);
                    const int xc1 = min(max(x0 + 1, 0), XD - 1);
                    const int yc0 = min(max(y0, 0), XD - 1);
                    const int yc1 = min(max(y0 + 1, 0), XD - 1);
                    As[base + s] = make_int4(((xc0 * XD + yc0) * XD) * 4, ((xc0 * XD + yc1) * XD) * 4,
                                             ((xc1 * XD + yc0) * XD) * 4, ((xc1 * XD + yc1) * XD) * 4);
                    Ws[base + s] = make_float4(wx0 * wy0, wx0 * wy1, wx1 * wy0, wx1 * wy1);
                } else {
                    As[base + s] = make_int4(0, 0, 0, 0);
                    Ws[base + s] = make_float4(0.0f, 0.0f, 0.0f, 0.0f);
                }
            }
        }
        __syncthreads();

        const char* volb = (const char*)vol + (lane << 4);

        // Mainloop over both lists: 8 warps, unroll 2, stride 16
        // -> 8 x LDG.128 in flight + 32 FFMA per trip.
        float4 SA = make_float4(0.0f, 0.0f, 0.0f, 0.0f);
        float4 SB = make_float4(0.0f, 0.0f, 0.0f, 0.0f);
        #pragma unroll 1
        for (int rr = 0; rr < 2; ++rr) {
            const int lo = rr ? LA : 0;
            const int hi = rr ? (LA + LB) : LA;
            float4 S = make_float4(0.0f, 0.0f, 0.0f, 0.0f);
            for (int m = lo + 2 * w; m < hi; m += 16) {
                const int4   A0 = As[m];
                const int4   A1 = As[m + 1];
                const float4 W0 = Ws[m];
                const float4 W1 = Ws[m + 1];
                const float4 r0 = __ldg((const float4*)(volb + A0.x));
                const float4 r1 = __ldg((const float4*)(volb + A0.y));
                const float4 r2 = __ldg((const float4*)(volb + A0.z));
                const float4 r3 = __ldg((const float4*)(volb + A0.w));
                const float4 r4 = __ldg((const float4*)(volb + A1.x));
                const float4 r5 = __ldg((const float4*)(volb + A1.y));
                const float4 r6 = __ldg((const float4*)(volb + A1.z));
                const float4 r7 = __ldg((const float4*)(volb + A1.w));
                S.x = fmaf(W0.x, r0.x, S.x); S.y = fmaf(W0.x, r0.y, S.y);
                S.z = fmaf(W0.x, r0.z, S.z); S.w = fmaf(W0.x, r0.w, S.w);
                S.x = fmaf(W0.y, r1.x, S.x); S.y = fmaf(W0.y, r1.y, S.y);
                S.z = fmaf(W0.y, r1.z, S.z); S.w = fmaf(W0.y, r1.w, S.w);
                S.x = fmaf(W0.z, r2.x, S.x); S.y = fmaf(W0.z, r2.y, S.y);
                S.z = fmaf(W0.z, r2.z, S.z); S.w = fmaf(W0.z, r2.w, S.w);
                S.x = fmaf(W0.w, r3.x, S.x); S.y = fmaf(W0.w, r3.y, S.y);
                S.z = fmaf(W0.w, r3.z, S.z); S.w = fmaf(W0.w, r3.w, S.w);
                S.x = fmaf(W1.x, r4.x, S.x); S.y = fmaf(W1.x, r4.y, S.y);
                S.z = fmaf(W1.x, r4.z, S.z); S.w = fmaf(W1.x, r4.w, S.w);
                S.x = fmaf(W1.y, r5.x, S.x); S.y = fmaf(W1.y, r5.y, S.y);
                S.z = fmaf(W1.y, r5.z, S.z); S.w = fmaf(W1.y, r5.w, S.w);
                S.x = fmaf(W1.z, r6.x, S.x); S.y = fmaf(W1.z, r6.y, S.y);
                S.z = fmaf(W1.z, r6.z, S.z); S.w = fmaf(W1.z, r6.w, S.w);
                S.x = fmaf(W1.w, r7.x, S.x); S.y = fmaf(W1.w, r7.y, S.y);
                S.z = fmaf(W1.w, r7.z, S.z); S.w = fmaf(W1.w, r7.w, S.w);
            }
            if (rr == 0) SA = S; else SB = S;
        }
        Red[0][w][lane * 4 + 0] = SA.x;
        Red[0][w][lane * 4 + 1] = SA.y;
        Red[0][w][lane * 4 + 2] = SA.z;
        Red[0][w][lane * 4 + 3] = SA.w;
        Red[1][w][lane * 4 + 0] = SB.x;
        Red[1][w][lane * 4 + 1] = SB.y;
        Red[1][w][lane * 4 + 2] = SB.z;
        Red[1][w][lane * 4 + 3] = SB.w;
        __syncthreads();

        {
            const int r = tid >> 7;
            const int z = tid & 127;
            float acc = 0.0f;
            #pragma unroll
            for (int g = 0; g < 8; ++g) acc += Red[r][g][z];
            const int jj = r ? jB : jA;
            out[((n * XD) + jj) * XD + z] = acc * (float)SCALE_D;
        }
    } else {
        // General path: per-pixel trilinear gather; thread handles (ray = tid>>7, z = tid&127).
        const int r = tid >> 7;
        const int z = tid & 127;
        const float jc = r ? jcB : jcA;
        const int  jj = r ? jB : jA;
        const float kc = (float)z - 63.5f;
        const float bx = fmaf(kc, vx, fmaf(jc, ux, dx)) + 63.5f;
        const float by = fmaf(kc, vy, fmaf(jc, uy, dy)) + 63.5f;
        const float bz = fmaf(kc, vz, fmaf(jc, uz, dz)) + 63.5f;

        float tlo = -3.0e38f, thi = 3.0e38f;
        bool empty = false;
        slab_axis(rx, bx, tlo, thi, empty);
        slab_axis(ry, by, tlo, thi, empty);
        slab_axis(rz, bz, tlo, thi, empty);

        int i0 = 0, i1 = -1;
        if (!empty && thi >= tlo) {
            i0 = max(0, (int)ceilf((tlo - t0) / dt) - 1);
            i1 = min(NDEPTH - 1, (int)floorf((thi - t0) / dt) + 1);
        }

        float sum = 0.0f;
        for (int i = i0; i <= i1; ++i) {
            const float t  = fmaf((float)i, dt, t0);
            const float px = fmaf(t, rx, bx);
            const float py = fmaf(t, ry, by);
            const float pz = fmaf(t, rz, bz);

            const float x0f = floorf(px);
            const float y0f = floorf(py);
            const float z0f = floorf(pz);
            const float fx = px - x0f;
            const float fy = py - y0f;
            const float fz = pz - z0f;
            const int x0 = (int)x0f;
            const int y0 = (int)y0f;
            const int z0 = (int)z0f;

            const int a = x0 * (XD * XD) + y0 * XD + z0;

            const bool xv0 = ((unsigned)x0 < (unsigned)XD);
            const bool xv1 = ((unsigned)(x0 + 1) < (unsigned)XD);
            const bool yv0 = ((unsigned)y0 < (unsigned)XD);
            const bool yv1 = ((unsigned)(y0 + 1) < (unsigned)XD);
            const bool zv0 = ((unsigned)z0 < (unsigned)XD);
            const bool zv1 = ((unsigned)(z0 + 1) < (unsigned)XD);

            const float v000 = (xv0 & yv0 & zv0) ? __ldg(vol + a)                    : 0.0f;
            const float v001 = (xv0 & yv0 & zv1) ? __ldg(vol + a + 1)                : 0.0f;
            const float v010 = (xv0 & yv1 & zv0) ? __ldg(vol + a + XD)               : 0.0f;
            const float v011 = (xv0 & yv1 & zv1) ? __ldg(vol + a + XD + 1)           : 0.0f;
            const float v100 = (xv1 & yv0 & zv0) ? __ldg(vol + a + XD * XD)          : 0.0f;
            const float v101 = (xv1 & yv0 & zv1) ? __ldg(vol + a + XD * XD + 1)      : 0.0f;
            const float v110 = (xv1 & yv1 & zv0) ? __ldg(vol + a + XD * XD + XD)     : 0.0f;
            const float v111 = (xv1 & yv1 & zv1) ? __ldg(vol + a + XD * XD + XD + 1) : 0.0f;

            const float c00 = fmaf(fz, v001 - v000, v000);
            const float c01 = fmaf(fz, v011 - v010, v010);
            const float c10 = fmaf(fz, v101 - v100, v100);
            const float c11 = fmaf(fz, v111 - v110, v110);
            const float c0  = fmaf(fy, c01 - c00, c00);
            const float c1  = fmaf(fy, c11 - c10, c10);
            sum += fmaf(fx, c1 - c0, c0);
        }
        out[((n * XD) + jj) * XD + z] = sum * (float)SCALE_D;
    }
}

extern "C" void kernel_launch(void* const* d_in, const int* in_sizes, int n_in,
                              void* d_out, int out_size) {
    const float* vol = (const float*)d_in[0];
    const float* vec = (const float*)d_in[1];
    float* out = (float*)d_out;

    const int N = in_sizes[1] / 12;
    dim3 grid(XD / 2, N);
    dim3 block(256);
    projector_kernel<<<grid, block>>>(vol, vec, out);
}

// round 12
// speedup vs baseline: 1.0560x; 1.0560x over previous
#include <cuda_runtime.h>
#include <math.h>

#define XD 128
#define NDEPTH 222
#define MPAD 232
// max_extent = sqrt(3*(64^2)) * 1.5
static constexpr double MAX_EXTENT_D = 166.27687752661222232;
static constexpr double DT_D         = 2.0 * MAX_EXTENT_D / (NDEPTH - 1);
static constexpr double SCALE_D      = 2.0 * MAX_EXTENT_D / NDEPTH;

__device__ __forceinline__ void slab_axis(float r, float b, float& tlo, float& thi, bool& empty) {
    if (fabsf(r) > 1e-12f) {
        float inv = __frcp_rn(r);
        float ta = (-1.0f - b) * inv;
        float tb = (128.0f - b) * inv;
        tlo = fmaxf(tlo, fminf(ta, tb));
        thi = fminf(thi, fmaxf(ta, tb));
    } else if (b <= -1.0f || b >= 128.0f) {
        empty = true;
    }
}

__global__ void __launch_bounds__(128, 8)
projector_kernel(const float* __restrict__ vol,
                 const float* __restrict__ vec,
                 float* __restrict__ out) {
    const int tid = threadIdx.x;
    const int j   = blockIdx.x;
    const int n   = blockIdx.y;

    const float* V = vec + n * 12;
    const float rx = __ldg(V + 0), ry = __ldg(V + 1), rz = __ldg(V + 2);
    const float dx = __ldg(V + 3), dy = __ldg(V + 4), dz = __ldg(V + 5);
    const float ux = __ldg(V + 6), uy = __ldg(V + 7), uz = __ldg(V + 8);
    const float vx = __ldg(V + 9), vy = __ldg(V + 10), vz = __ldg(V + 11);

    const float t0 = (float)(-MAX_EXTENT_D);
    const float dt = (float)DT_D;
    const float jc = (float)j - 63.5f;

    // Per-step metadata: float4 {w00', w01', w10, w11}.
    // w00'/w01' carry the 14-bit base row index in their LOW 7 mantissa bits each
    // (rel. perturbation <= 2^-17 — far below the error budget). The step's 4 rows
    // live at base + {0, 512, 65536, 66048} bytes (y-pairs contiguous, x-pairs 64KB).
    __shared__ float4 Ms[MPAD];
    __shared__ float  Red[4][132];   // padded reduce buffer

    // Fast path: z-axis-aligned geometry -> per-block-uniform (x,y) sample,
    // z index is EXACTLY the pixel k with fz = 0 (single z-tap, weight 1).
    const bool fast = (rz == 0.0f) & (uz == 0.0f) & (dz == 0.0f) &
                      (vx == 0.0f) & (vy == 0.0f) & (vz == 1.0f);

    if (fast) {
        const int w    = tid >> 5;   // warp id (0..3): depth-split group
        const int lane = tid & 31;   // covers z = 4*lane .. 4*lane+3

        const float bx = fmaf(jc, ux, dx) + 63.5f;
        const float by = fmaf(jc, uy, dy) + 63.5f;

        float tlo = -3.0e38f, thi = 3.0e38f;
        bool empty = false;
        slab_axis(rx, bx, tlo, thi, empty);
        slab_axis(ry, by, tlo, thi, empty);

        int i0 = 0, cnt = 0;
        if (!empty && thi >= tlo) {
            i0 = max(0, (int)ceilf((tlo - t0) / dt) - 1);
            int i1 = min(NDEPTH - 1, (int)floorf((thi - t0) / dt) + 1);
            cnt = i1 - i0 + 1;
            if (cnt < 0) cnt = 0;
        }
        const int cntPad = (cnt + 7) & ~7;   // pad to unroll granularity

        // Metadata phase.
        for (int m = tid; m < cntPad; m += 128) {
            if (m < cnt) {
                const float t  = fmaf((float)(i0 + m), dt, t0);
                const float px = fmaf(t, rx, bx);
                const float py = fmaf(t, ry, by);
                const float x0f = floorf(px);
                const float y0f = floorf(py);
                const float fx = px - x0f;
                const float fy = py - y0f;
                const int x0 = (int)x0f;
                const int y0 = (int)y0f;
                const float wx0 = ((unsigned)x0       < (unsigned)XD) ? (1.0f - fx) : 0.0f;
                const float wx1 = ((unsigned)(x0 + 1) < (unsigned)XD) ? fx          : 0.0f;
                const float wy0 = ((unsigned)y0       < (unsigned)XD) ? (1.0f - fy) : 0.0f;
                const float wy1 = ((unsigned)(y0 + 1) < (unsigned)XD) ? fy          : 0.0f;

                // Base-shift per axis: base cell in [0,126]; any shifted-out cell
                // has zero weight, any valid cell keeps its exact slot/address.
                int   bxc;  float X0, X1;
                if (x0 < 0)        { bxc = 0;   X0 = wx1; X1 = 0.0f; }
                else if (x0 > 126) { bxc = 126; X0 = 0.0f; X1 = wx0; }
                else               { bxc = x0;  X0 = wx0; X1 = wx1; }
                int   byc;  float Y0, Y1;
                if (y0 < 0)        { byc = 0;   Y0 = wy1; Y1 = 0.0f; }
                else if (y0 > 126) { byc = 126; Y0 = 0.0f; Y1 = wy0; }
                else               { byc = y0;  Y0 = wy0; Y1 = wy1; }

                const unsigned ridx = (unsigned)(bxc * XD + byc);   // <= 16254, 14 bits
                const float w00 = X0 * Y0;
                const float w01 = X0 * Y1;
                const float w10 = X1 * Y0;
                const float w11 = X1 * Y1;
                const unsigned u00 = (__float_as_uint(w00) & ~0x7Fu) | (ridx >> 7);
                const unsigned u01 = (__float_as_uint(w01) & ~0x7Fu) | (ridx & 0x7Fu);
                Ms[m] = make_float4(__uint_as_float(u00), __uint_as_float(u01), w10, w11);
            } else {
                Ms[m] = make_float4(0.0f, 0.0f, 0.0f, 0.0f);   // base 0, weights 0
            }
        }
        __syncthreads();

        // Mainloop: per trip 2 steps -> 2 LDS.128 + 8 LDG.128(+imm) + 32 FFMA.
        const char* volb = (const char*)vol + (lane << 4);
        float4 S = make_float4(0.0f, 0.0f, 0.0f, 0.0f);
        for (int m = 2 * w; m < cntPad; m += 8) {
            const float4 W0 = Ms[m];
            const float4 W1 = Ms[m + 1];
            const unsigned a0 = __float_as_uint(W0.x);
            const unsigned b0 = __float_as_uint(W0.y);
            const unsigned a1 = __float_as_uint(W1.x);
            const unsigned b1 = __float_as_uint(W1.y);
            const unsigned r0i = ((a0 & 0x7Fu) << 7) | (b0 & 0x7Fu);
            const unsigned r1i = ((a1 & 0x7Fu) << 7) | (b1 & 0x7Fu);
            const char* p0 = volb + ((size_t)r0i << 9);
            const char* p1 = volb + ((size_t)r1i << 9);
            const float4 q00 = __ldg((const float4*)(p0));
            const float4 q01 = __ldg((const float4*)(p0 + 512));
            const float4 q10 = __ldg((const float4*)(p0 + 65536));
            const float4 q11 = __ldg((const float4*)(p0 + 66048));
            const float4 q20 = __ldg((const float4*)(p1));
            const float4 q21 = __ldg((const float4*)(p1 + 512));
            const float4 q30 = __ldg((const float4*)(p1 + 65536));
            const float4 q31 = __ldg((const float4*)(p1 + 66048));
            S.x = fmaf(W0.x, q00.x, S.x); S.y = fmaf(W0.x, q00.y, S.y);
            S.z = fmaf(W0.x, q00.z, S.z); S.w = fmaf(W0.x, q00.w, S.w);
            S.x = fmaf(W0.y, q01.x, S.x); S.y = fmaf(W0.y, q01.y, S.y);
            S.z = fmaf(W0.y, q01.z, S.z); S.w = fmaf(W0.y, q01.w, S.w);
            S.x = fmaf(W0.z, q10.x, S.x); S.y = fmaf(W0.z, q10.y, S.y);
            S.z = fmaf(W0.z, q10.z, S.z); S.w = fmaf(W0.z, q10.w, S.w);
            S.x = fmaf(W0.w, q11.x, S.x); S.y = fmaf(W0.w, q11.y, S.y);
            S.z = fmaf(W0.w, q11.z, S.z); S.w = fmaf(W0.w, q11.w, S.w);
            S.x = fmaf(W1.x, q20.x, S.x); S.y = fmaf(W1.x, q20.y, S.y);
            S.z = fmaf(W1.x, q20.z, S.z); S.w = fmaf(W1.x, q20.w, S.w);
            S.x = fmaf(W1.y, q21.x, S.x); S.y = fmaf(W1.y, q21.y, S.y);
            S.z = fmaf(W1.y, q21.z, S.z); S.w = fmaf(W1.y, q21.w, S.w);
            S.x = fmaf(W1.z, q30.x, S.x); S.y = fmaf(W1.z, q30.y, S.y);
            S.z = fmaf(W1.z, q30.z, S.z); S.w = fmaf(W1.z, q30.w, S.w);
            S.x = fmaf(W1.w, q31.x, S.x); S.y = fmaf(W1.w, q31.y, S.y);
            S.z = fmaf(W1.w, q31.z, S.z); S.w = fmaf(W1.w, q31.w, S.w);
        }
        Red[w][lane * 4 + 0] = S.x;
        Red[w][lane * 4 + 1] = S.y;
        Red[w][lane * 4 + 2] = S.z;
        Red[w][lane * 4 + 3] = S.w;
        __syncthreads();

        const float acc = Red[0][tid] + Red[1][tid] + Red[2][tid] + Red[3][tid];
        out[((n * XD) + j) * XD + tid] = acc * (float)SCALE_D;
    } else {
        // General path: per-pixel trilinear gather (one thread per z, full depth).
        const int z = tid;
        const float kc = (float)z - 63.5f;
        const float bx = fmaf(kc, vx, fmaf(jc, ux, dx)) + 63.5f;
        const float by = fmaf(kc, vy, fmaf(jc, uy, dy)) + 63.5f;
        const float bz = fmaf(kc, vz, fmaf(jc, uz, dz)) + 63.5f;

        float tlo = -3.0e38f, thi = 3.0e38f;
        bool empty = false;
        slab_axis(rx, bx, tlo, thi, empty);
        slab_axis(ry, by, tlo, thi, empty);
        slab_axis(rz, bz, tlo, thi, empty);

        int i0 = 0, i1 = -1;
        if (!empty && thi >= tlo) {
            i0 = max(0, (int)ceilf((tlo - t0) / dt) - 1);
            i1 = min(NDEPTH - 1, (int)floorf((thi - t0) / dt) + 1);
        }

        float sum = 0.0f;
        for (int i = i0; i <= i1; ++i) {
            const float t  = fmaf((float)i, dt, t0);
            const float px = fmaf(t, rx, bx);
            const float py = fmaf(t, ry, by);
            const float pz = fmaf(t, rz, bz);

            const float x0f = floorf(px);
            const float y0f = floorf(py);
            const float z0f = floorf(pz);
            const float fx = px - x0f;
            const float fy = py - y0f;
            const float fz = pz - z0f;
            const int x0 = (int)x0f;
            const int y0 = (int)y0f;
            const int z0 = (int)z0f;

            const int a = x0 * (XD * XD) + y0 * XD + z0;

            const bool xv0 = ((unsigned)x0 < (unsigned)XD);
            const bool xv1 = ((unsigned)(x0 + 1) < (unsigned)XD);
            const bool yv0 = ((unsigned)y0 < (unsigned)XD);
            const bool yv1 = ((unsigned)(y0 + 1) < (unsigned)XD);
            const bool zv0 = ((unsigned)z0 < (unsigned)XD);
            const bool zv1 = ((unsigned)(z0 + 1) < (unsigned)XD);

            const float v000 = (xv0 & yv0 & zv0) ? __ldg(vol + a)                    : 0.0f;
            const float v001 = (xv0 & yv0 & zv1) ? __ldg(vol + a + 1)                : 0.0f;
            const float v010 = (xv0 & yv1 & zv0) ? __ldg(vol + a + XD)               : 0.0f;
            const float v011 = (xv0 & yv1 & zv1) ? __ldg(vol + a + XD + 1)           : 0.0f;
            const float v100 = (xv1 & yv0 & zv0) ? __ldg(vol + a + XD * XD)          : 0.0f;
            const float v101 = (xv1 & yv0 & zv1) ? __ldg(vol + a + XD * XD + 1)      : 0.0f;
            const float v110 = (xv1 & yv1 & zv0) ? __ldg(vol + a + XD * XD + XD)     : 0.0f;
            const float v111 = (xv1 & yv1 & zv1) ? __ldg(vol + a + XD * XD + XD + 1) : 0.0f;

            const float c00 = fmaf(fz, v001 - v000, v000);
            const float c01 = fmaf(fz, v011 - v010, v010);
            const float c10 = fmaf(fz, v101 - v100, v100);
            const float c11 = fmaf(fz, v111 - v110, v110);
            const float c0  = fmaf(fy, c01 - c00, c00);
            const float c1  = fmaf(fy, c11 - c10, c10);
            sum += fmaf(fx, c1 - c0, c0);
        }
        out[((n * XD) + j) * XD + z] = sum * (float)SCALE_D;
    }
}

extern "C" void kernel_launch(void* const* d_in, const int* in_sizes, int n_in,
                              void* d_out, int out_size) {
    const float* vol = (const float*)d_in[0];
    const float* vec = (const float*)d_in[1];
    float* out = (float*)d_out;

    const int N = in_sizes[1] / 12;
    dim3 grid(XD, N);
    dim3 block(128);
    projector_kernel<<<grid, block>>>(vol, vec, out);
}

// round 13
// speedup vs baseline: 1.2281x; 1.1629x over previous
#include <cuda_runtime.h>
#include <math.h>

#define XD 128
#define NDEPTH 222
#define MPAD 240
// max_extent = sqrt(3*(64^2)) * 1.5
static constexpr double MAX_EXTENT_D = 166.27687752661222232;
static constexpr double DT_D         = 2.0 * MAX_EXTENT_D / (NDEPTH - 1);
static constexpr double SCALE_D      = 2.0 * MAX_EXTENT_D / NDEPTH;

__device__ __forceinline__ void slab_axis(float r, float b, float& tlo, float& thi, bool& empty) {
    if (fabsf(r) > 1e-12f) {
        float inv = __frcp_rn(r);
        float ta = (-1.0f - b) * inv;
        float tb = (128.0f - b) * inv;
        tlo = fmaxf(tlo, fminf(ta, tb));
        thi = fminf(thi, fmaxf(ta, tb));
    } else if (b <= -1.0f || b >= 128.0f) {
        empty = true;
    }
}

__global__ void __launch_bounds__(128, 7)
projector_kernel(const float* __restrict__ vol,
                 const float* __restrict__ vec,
                 float* __restrict__ out) {
    const int tid = threadIdx.x;
    const int j   = blockIdx.x;
    const int n   = blockIdx.y;

    const float* V = vec + n * 12;
    const float rx = __ldg(V + 0), ry = __ldg(V + 1), rz = __ldg(V + 2);
    const float dx = __ldg(V + 3), dy = __ldg(V + 4), dz = __ldg(V + 5);
    const float ux = __ldg(V + 6), uy = __ldg(V + 7), uz = __ldg(V + 8);
    const float vx = __ldg(V + 9), vy = __ldg(V + 10), vz = __ldg(V + 11);

    const float t0 = (float)(-MAX_EXTENT_D);
    const float dt = (float)DT_D;
    const float jc = (float)j - 63.5f;

    // Per-step metadata: float4 {w00', w01', w10, w11}; w00'/w01' carry the 14-bit
    // base row index in their LOW 7 mantissa bits each (rel. perturbation <= 2^-17).
    // The step's 4 rows sit at base + {0, 512, 65536, 66048} bytes.
    __shared__ float4 Ms[MPAD];
    __shared__ float  Red[4][132];   // padded reduce buffer

    // Fast path: z-axis-aligned geometry -> per-block-uniform (x,y) sample,
    // z index is EXACTLY the pixel k with fz = 0 (single z-tap, weight 1).
    const bool fast = (rz == 0.0f) & (uz == 0.0f) & (dz == 0.0f) &
                      (vx == 0.0f) & (vy == 0.0f) & (vz == 1.0f);

    if (fast) {
        const int w    = tid >> 5;   // warp id (0..3): depth-split group
        const int lane = tid & 31;   // covers z = 4*lane .. 4*lane+3

        const float bx = fmaf(jc, ux, dx) + 63.5f;
        const float by = fmaf(jc, uy, dy) + 63.5f;

        float tlo = -3.0e38f, thi = 3.0e38f;
        bool empty = false;
        slab_axis(rx, bx, tlo, thi, empty);
        slab_axis(ry, by, tlo, thi, empty);

        int i0 = 0, cnt = 0;
        if (!empty && thi >= tlo) {
            i0 = max(0, (int)ceilf((tlo - t0) / dt) - 1);
            int i1 = min(NDEPTH - 1, (int)floorf((thi - t0) / dt) + 1);
            cnt = i1 - i0 + 1;
            if (cnt < 0) cnt = 0;
        }
        // Pad to 4 warps x unroll-3 granularity (12); zero-weight tail entries.
        const int cntPad = ((cnt + 11) / 12) * 12;

        // Metadata phase.
        for (int m = tid; m < cntPad; m += 128) {
            if (m < cnt) {
                const float t  = fmaf((float)(i0 + m), dt, t0);
                const float px = fmaf(t, rx, bx);
                const float py = fmaf(t, ry, by);
                const float x0f = floorf(px);
                const float y0f = floorf(py);
                const float fx = px - x0f;
                const float fy = py - y0f;
                const int x0 = (int)x0f;
                const int y0 = (int)y0f;
                const float wx0 = ((unsigned)x0       < (unsigned)XD) ? (1.0f - fx) : 0.0f;
                const float wx1 = ((unsigned)(x0 + 1) < (unsigned)XD) ? fx          : 0.0f;
                const float wy0 = ((unsigned)y0       < (unsigned)XD) ? (1.0f - fy) : 0.0f;
                const float wy1 = ((unsigned)(y0 + 1) < (unsigned)XD) ? fy          : 0.0f;

                // Base-shift per axis: base cell in [0,126]; shifted-out cells have
                // zero weight; valid cells keep their exact slot/address.
                int   bxc;  float X0, X1;
                if (x0 < 0)        { bxc = 0;   X0 = wx1; X1 = 0.0f; }
                else if (x0 > 126) { bxc = 126; X0 = 0.0f; X1 = wx0; }
                else               { bxc = x0;  X0 = wx0; X1 = wx1; }
                int   byc;  float Y0, Y1;
                if (y0 < 0)        { byc = 0;   Y0 = wy1; Y1 = 0.0f; }
                else if (y0 > 126) { byc = 126; Y0 = 0.0f; Y1 = wy0; }
                else               { byc = y0;  Y0 = wy0; Y1 = wy1; }

                const unsigned ridx = (unsigned)(bxc * XD + byc);   // 14 bits
                const float w00 = X0 * Y0;
                const float w01 = X0 * Y1;
                const float w10 = X1 * Y0;
                const float w11 = X1 * Y1;
                const unsigned u00 = (__float_as_uint(w00) & ~0x7Fu) | (ridx >> 7);
                const unsigned u01 = (__float_as_uint(w01) & ~0x7Fu) | (ridx & 0x7Fu);
                Ms[m] = make_float4(__uint_as_float(u00), __uint_as_float(u01), w10, w11);
            } else {
                Ms[m] = make_float4(0.0f, 0.0f, 0.0f, 0.0f);   // base 0, weights 0
            }
        }
        __syncthreads();

        // Mainloop: 3 steps/trip -> 3 LDS.128 + 12 LDG.128 in flight + 48 FFMA.
        const char* volb = (const char*)vol + (lane << 4);
        float4 S = make_float4(0.0f, 0.0f, 0.0f, 0.0f);
        for (int m = 3 * w; m < cntPad; m += 12) {
            const float4 W0 = Ms[m];
            const float4 W1 = Ms[m + 1];
            const float4 W2 = Ms[m + 2];
            const unsigned r0i = ((__float_as_uint(W0.x) & 0x7Fu) << 7) | (__float_as_uint(W0.y) & 0x7Fu);
            const unsigned r1i = ((__float_as_uint(W1.x) & 0x7Fu) << 7) | (__float_as_uint(W1.y) & 0x7Fu);
            const unsigned r2i = ((__float_as_uint(W2.x) & 0x7Fu) << 7) | (__float_as_uint(W2.y) & 0x7Fu);
            const char* p0 = volb + ((size_t)r0i << 9);
            const char* p1 = volb + ((size_t)r1i << 9);
            const char* p2 = volb + ((size_t)r2i << 9);
            const float4 q00 = __ldg((const float4*)(p0));
            const float4 q01 = __ldg((const float4*)(p0 + 512));
            const float4 q02 = __ldg((const float4*)(p0 + 65536));
            const float4 q03 = __ldg((const float4*)(p0 + 66048));
            const float4 q10 = __ldg((const float4*)(p1));
            const float4 q11 = __ldg((const float4*)(p1 + 512));
            const float4 q12 = __ldg((const float4*)(p1 + 65536));
            const float4 q13 = __ldg((const float4*)(p1 + 66048));
            const float4 q20 = __ldg((const float4*)(p2));
            const float4 q21 = __ldg((const float4*)(p2 + 512));
            const float4 q22 = __ldg((const float4*)(p2 + 65536));
            const float4 q23 = __ldg((const float4*)(p2 + 66048));
            S.x = fmaf(W0.x, q00.x, S.x); S.y = fmaf(W0.x, q00.y, S.y);
            S.z = fmaf(W0.x, q00.z, S.z); S.w = fmaf(W0.x, q00.w, S.w);
            S.x = fmaf(W0.y, q01.x, S.x); S.y = fmaf(W0.y, q01.y, S.y);
            S.z = fmaf(W0.y, q01.z, S.z); S.w = fmaf(W0.y, q01.w, S.w);
            S.x = fmaf(W0.z, q02.x, S.x); S.y = fmaf(W0.z, q02.y, S.y);
            S.z = fmaf(W0.z, q02.z, S.z); S.w = fmaf(W0.z, q02.w, S.w);
            S.x = fmaf(W0.w, q03.x, S.x); S.y = fmaf(W0.w, q03.y, S.y);
            S.z = fmaf(W0.w, q03.z, S.z); S.w = fmaf(W0.w, q03.w, S.w);
            S.x = fmaf(W1.x, q10.x, S.x); S.y = fmaf(W1.x, q10.y, S.y);
            S.z = fmaf(W1.x, q10.z, S.z); S.w = fmaf(W1.x, q10.w, S.w);
            S.x = fmaf(W1.y, q11.x, S.x); S.y = fmaf(W1.y, q11.y, S.y);
            S.z = fmaf(W1.y, q11.z, S.z); S.w = fmaf(W1.y, q11.w, S.w);
            S.x = fmaf(W1.z, q12.x, S.x); S.y = fmaf(W1.z, q12.y, S.y);
            S.z = fmaf(W1.z, q12.z, S.z); S.w = fmaf(W1.z, q12.w, S.w);
            S.x = fmaf(W1.w, q13.x, S.x); S.y = fmaf(W1.w, q13.y, S.y);
            S.z = fmaf(W1.w, q13.z, S.z); S.w = fmaf(W1.w, q13.w, S.w);
            S.x = fmaf(W2.x, q20.x, S.x); S.y = fmaf(W2.x, q20.y, S.y);
            S.z = fmaf(W2.x, q20.z, S.z); S.w = fmaf(W2.x, q20.w, S.w);
            S.x = fmaf(W2.y, q21.x, S.x); S.y = fmaf(W2.y, q21.y, S.y);
            S.z = fmaf(W2.y, q21.z, S.z); S.w = fmaf(W2.y, q21.w, S.w);
            S.x = fmaf(W2.z, q22.x, S.x); S.y = fmaf(W2.z, q22.y, S.y);
            S.z = fmaf(W2.z, q22.z, S.z); S.w = fmaf(W2.z, q22.w, S.w);
            S.x = fmaf(W2.w, q23.x, S.x); S.y = fmaf(W2.w, q23.y, S.y);
            S.z = fmaf(W2.w, q23.z, S.z); S.w = fmaf(W2.w, q23.w, S.w);
        }
        Red[w][lane * 4 + 0] = S.x;
        Red[w][lane * 4 + 1] = S.y;
        Red[w][lane * 4 + 2] = S.z;
        Red[w][lane * 4 + 3] = S.w;
        __syncthreads();

        const float acc = Red[0][tid] + Red[1][tid] + Red[2][tid] + Red[3][tid];
        out[((n * XD) + j) * XD + tid] = acc * (float)SCALE_D;
    } else {
        // General path: per-pixel trilinear gather (one thread per z, full depth).
        const int z = tid;
        const float kc = (float)z - 63.5f;
        const float bx = fmaf(kc, vx, fmaf(jc, ux, dx)) + 63.5f;
        const float by = fmaf(kc, vy, fmaf(jc, uy, dy)) + 63.5f;
        const float bz = fmaf(kc, vz, fmaf(jc, uz, dz)) + 63.5f;

        float tlo = -3.0e38f, thi = 3.0e38f;
        bool empty = false;
        slab_axis(rx, bx, tlo, thi, empty);
        slab_axis(ry, by, tlo, thi, empty);
        slab_axis(rz, bz, tlo, thi, empty);

        int i0 = 0, i1 = -1;
        if (!empty && thi >= tlo) {
            i0 = max(0, (int)ceilf((tlo - t0) / dt) - 1);
            i1 = min(NDEPTH - 1, (int)floorf((thi - t0) / dt) + 1);
        }

        float sum = 0.0f;
        for (int i = i0; i <= i1; ++i) {
            const float t  = fmaf((float)i, dt, t0);
            const float px = fmaf(t, rx, bx);
            const float py = fmaf(t, ry, by);
            const float pz = fmaf(t, rz, bz);

            const float x0f = floorf(px);
            const float y0f = floorf(py);
            const float z0f = floorf(pz);
            const float fx = px - x0f;
            const float fy = py - y0f;
            const float fz = pz - z0f;
            const int x0 = (int)x0f;
            const int y0 = (int)y0f;
            const int z0 = (int)z0f;

            const int a = x0 * (XD * XD) + y0 * XD + z0;

            const bool xv0 = ((unsigned)x0 < (unsigned)XD);
            const bool xv1 = ((unsigned)(x0 + 1) < (unsigned)XD);
            const bool yv0 = ((unsigned)y0 < (unsigned)XD);
            const bool yv1 = ((unsigned)(y0 + 1) < (unsigned)XD);
            const bool zv0 = ((unsigned)z0 < (unsigned)XD);
            const bool zv1 = ((unsigned)(z0 + 1) < (unsigned)XD);

            const float v000 = (xv0 & yv0 & zv0) ? __ldg(vol + a)                    : 0.0f;
            const float v001 = (xv0 & yv0 & zv1) ? __ldg(vol + a + 1)                : 0.0f;
            const float v010 = (xv0 & yv1 & zv0) ? __ldg(vol + a + XD)               : 0.0f;
            const float v011 = (xv0 & yv1 & zv1) ? __ldg(vol + a + XD + 1)           : 0.0f;
            const float v100 = (xv1 & yv0 & zv0) ? __ldg(vol + a + XD * XD)          : 0.0f;
            const float v101 = (xv1 & yv0 & zv1) ? __ldg(vol + a + XD * XD + 1)      : 0.0f;
            const float v110 = (xv1 & yv1 & zv0) ? __ldg(vol + a + XD * XD + XD)     : 0.0f;
            const float v111 = (xv1 & yv1 & zv1) ? __ldg(vol + a + XD * XD + XD + 1) : 0.0f;

            const float c00 = fmaf(fz, v001 - v000, v000);
            const float c01 = fmaf(fz, v011 - v010, v010);
            const float c10 = fmaf(fz, v101 - v100, v100);
            const float c11 = fmaf(fz, v111 - v110, v110);
            const float c0  = fmaf(fy, c01 - c00, c00);
            const float c1  = fmaf(fy, c11 - c10, c10);
            sum += fmaf(fx, c1 - c0, c0);
        }
        out[((n * XD) + j) * XD + z] = sum * (float)SCALE_D;
    }
}

extern "C" void kernel_launch(void* const* d_in, const int* in_sizes, int n_in,
                              void* d_out, int out_size) {
    const float* vol = (const float*)d_in[0];
    const float* vec = (const float*)d_in[1];
    float* out = (float*)d_out;

    const int N = in_sizes[1] / 12;
    dim3 grid(XD, N);
    dim3 block(128);
    projector_kernel<<<grid, block>>>(vol, vec, out);
}